// round 5
// baseline (speedup 1.0000x reference)
#include <cuda_runtime.h>
#include <cstdint>
#include <cstddef>

#define BB 16
#define NN 8192
#define SS 1024
#define KK 32
#define R2C 0.04f          /* float(0.2**2) as JAX casts the python scalar */
#define EPSC 1e-5f
#define MTOT (BB*SS*KK)    /* 524288 positions */
#define OUT_OFF (BB*SS*3)  /* new_xyz occupies first 49152 floats of d_out */

// ---------------- device scratch (static allocation is the sanctioned path) ---
__device__ int    g_fps[BB*SS];
__device__ int    g_idx[BB*SS*KK];
__device__ float  g_y1[(size_t)MTOT*64];
__device__ float  g_y2[(size_t)MTOT*64];
__device__ float  g_y3[(size_t)MTOT*128];
__device__ double g_sum[3][128];
__device__ double g_sq[3][128];
__device__ float  g_scale[3][128];
__device__ float  g_shift[3][128];

// ---------------- init: zero stat accumulators (graph replays must be clean) --
__global__ void init_kernel() {
    int t = blockIdx.x * blockDim.x + threadIdx.x;
    if (t < 3 * 128) {
        ((double*)g_sum)[t] = 0.0;
        ((double*)g_sq)[t]  = 0.0;
    }
}

// ---------------- farthest point sampling: one CTA per batch -----------------
__global__ __launch_bounds__(1024) void fps_kernel(const float* __restrict__ xyz) {
    int b = blockIdx.x;
    int t = threadIdx.x;
    const float* xb = xyz + (size_t)b * NN * 3;

    float px[8], py[8], pz[8], dist[8];
#pragma unroll
    for (int i = 0; i < 8; i++) {
        int p = t + i * 1024;
        px[i] = xb[p*3+0];
        py[i] = xb[p*3+1];
        pz[i] = xb[p*3+2];
        dist[i] = 1e10f;
    }

    __shared__ float s_val[32];
    __shared__ int   s_idx[32];
    __shared__ int   s_far;
    if (t == 0) s_far = 0;
    __syncthreads();

    for (int it = 0; it < SS; it++) {
        int far = s_far;
        if (t == 0) g_fps[b * SS + it] = far;
        float cx = xb[far*3+0], cy = xb[far*3+1], cz = xb[far*3+2];

        float bestv = -1.0f; int besti = 0;
#pragma unroll
        for (int i = 0; i < 8; i++) {
            float dx = px[i] - cx, dy = py[i] - cy, dz = pz[i] - cz;
            float d = dx*dx + dy*dy + dz*dz;
            float nd = fminf(dist[i], d);
            dist[i] = nd;
            if (nd > bestv) { bestv = nd; besti = t + i * 1024; }
        }
        // warp argmax (ties -> smaller index, matching jnp.argmax)
#pragma unroll
        for (int off = 16; off; off >>= 1) {
            float ov = __shfl_down_sync(0xffffffffu, bestv, off);
            int   oi = __shfl_down_sync(0xffffffffu, besti, off);
            if (ov > bestv || (ov == bestv && oi < besti)) { bestv = ov; besti = oi; }
        }
        if ((t & 31) == 0) { s_val[t >> 5] = bestv; s_idx[t >> 5] = besti; }
        __syncthreads();
        if (t < 32) {
            bestv = s_val[t]; besti = s_idx[t];
#pragma unroll
            for (int off = 16; off; off >>= 1) {
                float ov = __shfl_down_sync(0xffffffffu, bestv, off);
                int   oi = __shfl_down_sync(0xffffffffu, besti, off);
                if (ov > bestv || (ov == bestv && oi < besti)) { bestv = ov; besti = oi; }
            }
            if (t == 0) s_far = besti;
        }
        __syncthreads();
    }
}

// ---------------- gather new_xyz into output ---------------------------------
__global__ void gather_newxyz_kernel(const float* __restrict__ xyz,
                                     float* __restrict__ out) {
    int i = blockIdx.x * blockDim.x + threadIdx.x;
    if (i < BB * SS) {
        int b = i >> 10;
        int j = g_fps[i];
        const float* p = xyz + ((size_t)b * NN + j) * 3;
        out[i*3+0] = p[0];
        out[i*3+1] = p[1];
        out[i*3+2] = p[2];
    }
}

// ---------------- ball query: one warp per query ------------------------------
__global__ void qb_kernel(const float* __restrict__ xyz) {
    int q = (blockIdx.x * blockDim.x + threadIdx.x) >> 5;  // 0..16383
    int lane = threadIdx.x & 31;
    int b = q >> 10;
    const float* xb = xyz + (size_t)b * NN * 3;
    int c = g_fps[q];
    float cx = xb[c*3+0], cy = xb[c*3+1], cz = xb[c*3+2];

    int cnt = 0;
    int first = 0;
    bool have_first = false;
    int* out = g_idx + (size_t)q * KK;

    for (int base = 0; base < NN; base += 32) {
        int p = base + lane;
        float dx = xb[p*3+0] - cx, dy = xb[p*3+1] - cy, dz = xb[p*3+2] - cz;
        float d = dx*dx + dy*dy + dz*dz;
        bool in = (d <= R2C);
        unsigned m = __ballot_sync(0xffffffffu, in);
        if (m) {
            int pos = cnt + __popc(m & ((1u << lane) - 1u));
            if (in && pos < KK) out[pos] = p;
            if (!have_first) { first = base + __ffs(m) - 1; have_first = true; }
            cnt += __popc(m);
            if (cnt >= KK) break;
        }
    }
    for (int pos = cnt + lane; pos < KK; pos += 32) out[pos] = first;
}

// ---------------- layer 1: gather + GEMM (K=67 -> 64) + stats ----------------
// 64 positions per block, 128 threads; thread tile = 4 pos x 8 out.
__global__ __launch_bounds__(128) void layer1_kernel(
    const float* __restrict__ xyz, const float* __restrict__ points,
    const float* __restrict__ newxyz,
    const float* __restrict__ w, const float* __restrict__ bias)
{
    __shared__ __align__(16) float Xs[67][64];
    __shared__ __align__(16) float Ws[67][64];
    __shared__ float sh_b[64], sh_sum[64], sh_sq[64];

    int t = threadIdx.x;
    size_t pos0 = (size_t)blockIdx.x * 64;

    for (int e = t; e < 64 * 67; e += 128) {
        int o = e / 67, c = e % 67;
        Ws[c][o] = w[e];
    }
    if (t < 64) { sh_b[t] = bias[t]; sh_sum[t] = 0.f; sh_sq[t] = 0.f; }

    {   // gather: 2 threads per position
        int p = t >> 1, half = t & 1;
        size_t pos = pos0 + p;
        int j = g_idx[pos];
        int b = (int)(pos >> 15);
        int s = (int)((pos >> 5) & 1023);
        const float4* prow = (const float4*)(points + ((size_t)b * NN + j) * 64) + half * 8;
#pragma unroll
        for (int i = 0; i < 8; i++) {
            float4 v = prow[i];
            int c = 3 + half * 32 + i * 4;
            Xs[c+0][p] = v.x; Xs[c+1][p] = v.y; Xs[c+2][p] = v.z; Xs[c+3][p] = v.w;
        }
        if (!half) {
            const float* xr = xyz + ((size_t)b * NN + j) * 3;
            const float* nr = newxyz + ((size_t)b * SS + s) * 3;
            Xs[0][p] = xr[0] - nr[0];
            Xs[1][p] = xr[1] - nr[1];
            Xs[2][p] = xr[2] - nr[2];
        }
    }
    __syncthreads();

    int px = t >> 3, ox = t & 7;
    float acc[4][8];
#pragma unroll
    for (int i = 0; i < 4; i++)
#pragma unroll
        for (int j = 0; j < 8; j++) acc[i][j] = sh_b[ox*8+j];

#pragma unroll 4
    for (int c = 0; c < 67; c++) {
        float4 xv  = *(const float4*)&Xs[c][px*4];
        float4 w0  = *(const float4*)&Ws[c][ox*8];
        float4 w1v = *(const float4*)&Ws[c][ox*8+4];
        float xa[4] = {xv.x, xv.y, xv.z, xv.w};
        float wa[8] = {w0.x, w0.y, w0.z, w0.w, w1v.x, w1v.y, w1v.z, w1v.w};
#pragma unroll
        for (int i = 0; i < 4; i++)
#pragma unroll
            for (int j = 0; j < 8; j++) acc[i][j] = fmaf(xa[i], wa[j], acc[i][j]);
    }

    float ssum[8], ssq[8];
#pragma unroll
    for (int j = 0; j < 8; j++) { ssum[j] = 0.f; ssq[j] = 0.f; }
#pragma unroll
    for (int i = 0; i < 4; i++) {
        size_t pp = pos0 + px*4 + i;
        *(float4*)&g_y1[pp*64 + ox*8]     = make_float4(acc[i][0], acc[i][1], acc[i][2], acc[i][3]);
        *(float4*)&g_y1[pp*64 + ox*8 + 4] = make_float4(acc[i][4], acc[i][5], acc[i][6], acc[i][7]);
#pragma unroll
        for (int j = 0; j < 8; j++) { ssum[j] += acc[i][j]; ssq[j] += acc[i][j]*acc[i][j]; }
    }
#pragma unroll
    for (int j = 0; j < 8; j++) {
        atomicAdd(&sh_sum[ox*8+j], ssum[j]);
        atomicAdd(&sh_sq[ox*8+j],  ssq[j]);
    }
    __syncthreads();
    if (t < 64) {
        atomicAdd(&g_sum[0][t], (double)sh_sum[t]);
        atomicAdd(&g_sq[0][t],  (double)sh_sq[t]);
    }
}

// ---------------- per-channel BN fold ----------------------------------------
__global__ void stats_kernel(int L, const float* __restrict__ gam,
                             const float* __restrict__ bet, int C) {
    int t = threadIdx.x;
    if (t < C) {
        double mean = g_sum[L][t] * (1.0 / (double)MTOT);
        double var  = g_sq[L][t]  * (1.0 / (double)MTOT) - mean * mean;
        float sc = gam[t] * rsqrtf((float)var + EPSC);
        g_scale[L][t] = sc;
        g_shift[L][t] = fmaf(-(float)mean, sc, bet[t]);
    }
}

// ---------------- layers 2/3: affine+relu(in) -> GEMM -> stats ---------------
// L=2: g_y1 -> g_y2 (64x64). L=3: g_y2 -> g_y3 (64x128).
template<int L, int NO, int POSB, int PX, int OX>
__global__ void layer_kernel(const float* __restrict__ w,
                             const float* __restrict__ bias)
{
    constexpr int THREADS = PX * OX;
    constexpr int TP = POSB / PX;           // 4
    constexpr int TO = NO / OX;             // 8 or 4
    constexpr int TPP = THREADS / POSB;     // threads per position
    constexpr int V4 = 16 / TPP;            // float4s per thread on load
    static_assert(TP == 4, "TP must be 4");

    const float* xin = (L == 2) ? g_y1 : g_y2;
    float*       y   = (L == 2) ? g_y2 : g_y3;

    __shared__ __align__(16) float Xs[64][POSB];
    __shared__ __align__(16) float Ws[64][NO];
    __shared__ float sh_b[NO], sh_sum[NO], sh_sq[NO];
    __shared__ float sh_scale[64], sh_shift[64];

    int t = threadIdx.x;
    size_t pos0 = (size_t)blockIdx.x * POSB;

    for (int e = t; e < NO * 64; e += THREADS) {
        int o = e >> 6, c = e & 63;
        Ws[c][o] = w[e];
    }
    if (t < NO) { sh_b[t] = bias[t]; sh_sum[t] = 0.f; sh_sq[t] = 0.f; }
    if (t < 64) { sh_scale[t] = g_scale[L-2][t]; sh_shift[t] = g_shift[L-2][t]; }
    __syncthreads();

    {   // staged input load with fused affine+relu
        int p = t / TPP, sub = t % TPP;
        const float4* row = (const float4*)(xin + (pos0 + p) * 64) + sub * V4;
#pragma unroll
        for (int i = 0; i < V4; i++) {
            float4 v = row[i];
            int c = (sub * V4 + i) * 4;
            Xs[c+0][p] = fmaxf(fmaf(v.x, sh_scale[c+0], sh_shift[c+0]), 0.f);
            Xs[c+1][p] = fmaxf(fmaf(v.y, sh_scale[c+1], sh_shift[c+1]), 0.f);
            Xs[c+2][p] = fmaxf(fmaf(v.z, sh_scale[c+2], sh_shift[c+2]), 0.f);
            Xs[c+3][p] = fmaxf(fmaf(v.w, sh_scale[c+3], sh_shift[c+3]), 0.f);
        }
    }
    __syncthreads();

    int px = t / OX, ox = t % OX;
    float acc[TP][TO];
#pragma unroll
    for (int i = 0; i < TP; i++)
#pragma unroll
        for (int j = 0; j < TO; j++) acc[i][j] = sh_b[ox*TO+j];

#pragma unroll 4
    for (int c = 0; c < 64; c++) {
        float4 xv = *(const float4*)&Xs[c][px*TP];
        float xa[4] = {xv.x, xv.y, xv.z, xv.w};
        float wa[TO];
#pragma unroll
        for (int j = 0; j < TO; j += 4) {
            float4 wv = *(const float4*)&Ws[c][ox*TO + j];
            wa[j] = wv.x; wa[j+1] = wv.y; wa[j+2] = wv.z; wa[j+3] = wv.w;
        }
#pragma unroll
        for (int i = 0; i < TP; i++)
#pragma unroll
            for (int j = 0; j < TO; j++) acc[i][j] = fmaf(xa[i], wa[j], acc[i][j]);
    }

    float ssum[TO], ssq[TO];
#pragma unroll
    for (int j = 0; j < TO; j++) { ssum[j] = 0.f; ssq[j] = 0.f; }
#pragma unroll
    for (int i = 0; i < TP; i++) {
        size_t pp = pos0 + px*TP + i;
#pragma unroll
        for (int j = 0; j < TO; j += 4) {
            *(float4*)&y[pp*NO + ox*TO + j] =
                make_float4(acc[i][j], acc[i][j+1], acc[i][j+2], acc[i][j+3]);
        }
#pragma unroll
        for (int j = 0; j < TO; j++) { ssum[j] += acc[i][j]; ssq[j] += acc[i][j]*acc[i][j]; }
    }
#pragma unroll
    for (int j = 0; j < TO; j++) {
        atomicAdd(&sh_sum[ox*TO+j], ssum[j]);
        atomicAdd(&sh_sq[ox*TO+j],  ssq[j]);
    }
    __syncthreads();
    if (t < NO) {
        atomicAdd(&g_sum[L-1][t], (double)sh_sum[t]);
        atomicAdd(&g_sq[L-1][t],  (double)sh_sq[t]);
    }
}

// ---------------- final: affine+relu + max over nsample + transpose ----------
__global__ void final_kernel(float* __restrict__ out) {
    int q = blockIdx.x;          // (b,s) 0..16383
    int o = threadIdx.x;         // channel 0..127
    float sc = g_scale[2][o], sh = g_shift[2][o];
    const float* base = g_y3 + (size_t)q * KK * 128;
    float m = 0.0f;  // relu output >= 0 and KK >= 1
#pragma unroll 8
    for (int k = 0; k < KK; k++) {
        float v = fmaxf(fmaf(base[k*128 + o], sc, sh), 0.f);
        m = fmaxf(m, v);
    }
    int b = q >> 10, s = q & 1023;
    out[OUT_OFF + ((size_t)b * 128 + o) * SS + s] = m;
}

// ---------------- launcher ----------------------------------------------------
extern "C" void kernel_launch(void* const* d_in, const int* in_sizes, int n_in,
                              void* d_out, int out_size) {
    (void)in_sizes; (void)n_in; (void)out_size;
    const float* xyz    = (const float*)d_in[0];
    const float* points = (const float*)d_in[1];
    const float* w1  = (const float*)d_in[2];
    const float* b1  = (const float*)d_in[3];
    const float* g1  = (const float*)d_in[4];
    const float* be1 = (const float*)d_in[5];
    const float* w2  = (const float*)d_in[6];
    const float* b2  = (const float*)d_in[7];
    const float* g2  = (const float*)d_in[8];
    const float* be2 = (const float*)d_in[9];
    const float* w3  = (const float*)d_in[10];
    const float* b3  = (const float*)d_in[11];
    const float* g3  = (const float*)d_in[12];
    const float* be3 = (const float*)d_in[13];
    float* out = (float*)d_out;

    init_kernel<<<1, 512>>>();
    fps_kernel<<<BB, 1024>>>(xyz);
    gather_newxyz_kernel<<<(BB*SS + 255) / 256, 256>>>(xyz, out);
    qb_kernel<<<(BB*SS) / 8, 256>>>(xyz);

    layer1_kernel<<<MTOT / 64, 128>>>(xyz, points, out, w1, b1);
    stats_kernel<<<1, 128>>>(0, g1, be1, 64);

    layer_kernel<2, 64, 64, 16, 8><<<MTOT / 64, 128>>>(w2, b2);
    stats_kernel<<<1, 128>>>(1, g2, be2, 64);

    layer_kernel<3, 128, 32, 8, 32><<<MTOT / 32, 256>>>(w3, b3);
    stats_kernel<<<1, 128>>>(2, g3, be3, 128);

    final_kernel<<<BB * SS, 128>>>(out);
}

// round 7
// speedup vs baseline: 1.1731x; 1.1731x over previous
#include <cuda_runtime.h>
#include <cstdint>
#include <cstddef>

#define BB 16
#define NN 8192
#define SS 1024
#define KK 32
#define R2C 0.04f          /* float(0.2**2) */
#define EPSC 1e-5f
#define MTOT (BB*SS*KK)    /* 524288 positions */
#define OUT_OFF (BB*SS*3)

typedef unsigned long long ull;

// ---------------- packed f32x2 helpers (sm_100+) ------------------------------
__device__ __forceinline__ ull fma2(ull a, ull b, ull c) {
    ull d; asm("fma.rn.f32x2 %0,%1,%2,%3;" : "=l"(d) : "l"(a), "l"(b), "l"(c)); return d;
}
__device__ __forceinline__ ull mul2(ull a, ull b) {
    ull d; asm("mul.rn.f32x2 %0,%1,%2;" : "=l"(d) : "l"(a), "l"(b)); return d;
}
__device__ __forceinline__ ull add2(ull a, ull b) {
    ull d; asm("add.rn.f32x2 %0,%1,%2;" : "=l"(d) : "l"(a), "l"(b)); return d;
}
__device__ __forceinline__ ull dup2(float x) {
    ull d; asm("mov.b64 %0,{%1,%1};" : "=l"(d) : "f"(x)); return d;
}
__device__ __forceinline__ ull pk2(float lo, float hi) {
    ull d; asm("mov.b64 %0,{%1,%2};" : "=l"(d) : "f"(lo), "f"(hi)); return d;
}
__device__ __forceinline__ float2 up2(ull v) {
    float2 r; asm("mov.b64 {%0,%1},%2;" : "=f"(r.x), "=f"(r.y) : "l"(v)); return r;
}

// ---------------- device scratch ----------------------------------------------
__device__ int    g_fps[BB*SS];
__device__ int    g_idx[BB*SS*KK];
__device__ float  g_y1[(size_t)MTOT*64];
__device__ float  g_y2[(size_t)MTOT*64];
__device__ float  g_mx[(size_t)BB*SS*128];
__device__ float  g_mn[(size_t)BB*SS*128];
__device__ double g_sum[3][128];
__device__ double g_sq[3][128];
__device__ float  g_scale[3][128];
__device__ float  g_shift[3][128];

// ---------------- init --------------------------------------------------------
__global__ void init_kernel() {
    int t = blockIdx.x * blockDim.x + threadIdx.x;
    if (t < 3 * 128) {
        ((double*)g_sum)[t] = 0.0;
        ((double*)g_sq)[t]  = 0.0;
    }
}

// ---------------- farthest point sampling: one CTA per batch -----------------
// Packed-f32x2 distance updates (bit-identical per lane to the scalar chain),
// strict-> in-thread argmax (first max = smallest index, matching jnp), and
// REDUX-based warp argmax: max of float bits (nonneg -> monotone), then max of
// ~idx among holders of the max -> smallest index.
__global__ __launch_bounds__(1024) void fps_kernel(const float* __restrict__ xyz) {
    int b = blockIdx.x;
    int t = threadIdx.x;
    const float* xb = xyz + (size_t)b * NN * 3;

    ull px2[4], py2[4], pz2[4];
    float dist[8];
#pragma unroll
    for (int j = 0; j < 4; j++) {
        int p0 = t + (2*j)   * 1024;
        int p1 = t + (2*j+1) * 1024;
        px2[j] = pk2(xb[p0*3+0], xb[p1*3+0]);
        py2[j] = pk2(xb[p0*3+1], xb[p1*3+1]);
        pz2[j] = pk2(xb[p0*3+2], xb[p1*3+2]);
    }
#pragma unroll
    for (int i = 0; i < 8; i++) dist[i] = 1e10f;

    __shared__ ull s_key[32];
    __shared__ int s_far;
    if (t == 0) s_far = 0;
    __syncthreads();

    for (int it = 0; it < SS; it++) {
        int far = s_far;
        if (t == 0) g_fps[b * SS + it] = far;
        float cx = xb[far*3+0], cy = xb[far*3+1], cz = xb[far*3+2];
        ull ncx = dup2(-cx), ncy = dup2(-cy), ncz = dup2(-cz);

        float bestv = -1.0f; int besti = 0;
#pragma unroll
        for (int j = 0; j < 4; j++) {
            ull dx = add2(px2[j], ncx);
            ull dy = add2(py2[j], ncy);
            ull dz = add2(pz2[j], ncz);
            ull d2 = mul2(dx, dx);
            d2 = fma2(dy, dy, d2);
            d2 = fma2(dz, dz, d2);
            float2 dd = up2(d2);
            float n0 = fminf(dist[2*j],   dd.x);
            float n1 = fminf(dist[2*j+1], dd.y);
            dist[2*j] = n0; dist[2*j+1] = n1;
            if (n0 > bestv) { bestv = n0; besti = t + (2*j)   * 1024; }
            if (n1 > bestv) { bestv = n1; besti = t + (2*j+1) * 1024; }
        }

        unsigned bits = __float_as_uint(bestv);           // bestv >= 0
        unsigned mh = __reduce_max_sync(0xffffffffu, bits);
        unsigned ml = __reduce_max_sync(0xffffffffu, (bits == mh) ? ~(unsigned)besti : 0u);
        if ((t & 31) == 0) s_key[t >> 5] = ((ull)mh << 32) | ml;
        __syncthreads();
        if (t < 32) {
            ull k = s_key[t];
            unsigned h2 = (unsigned)(k >> 32);
            unsigned m2 = __reduce_max_sync(0xffffffffu, h2);
            unsigned l2 = __reduce_max_sync(0xffffffffu, (h2 == m2) ? (unsigned)k : 0u);
            if (t == 0) s_far = (int)(~l2);
        }
        __syncthreads();
    }
}

// ---------------- gather new_xyz into output ---------------------------------
__global__ void gather_newxyz_kernel(const float* __restrict__ xyz,
                                     float* __restrict__ out) {
    int i = blockIdx.x * blockDim.x + threadIdx.x;
    if (i < BB * SS) {
        int b = i >> 10;
        int j = g_fps[i];
        const float* p = xyz + ((size_t)b * NN + j) * 3;
        out[i*3+0] = p[0];
        out[i*3+1] = p[1];
        out[i*3+2] = p[2];
    }
}

// ---------------- ball query: one warp per query ------------------------------
__global__ void qb_kernel(const float* __restrict__ xyz) {
    int q = (blockIdx.x * blockDim.x + threadIdx.x) >> 5;
    int lane = threadIdx.x & 31;
    int b = q >> 10;
    const float* xb = xyz + (size_t)b * NN * 3;
    int c = g_fps[q];
    float cx = xb[c*3+0], cy = xb[c*3+1], cz = xb[c*3+2];

    int cnt = 0;
    int first = 0;
    bool have_first = false;
    int* out = g_idx + (size_t)q * KK;

    for (int base = 0; base < NN; base += 32) {
        int p = base + lane;
        float dx = xb[p*3+0] - cx, dy = xb[p*3+1] - cy, dz = xb[p*3+2] - cz;
        float d = dx*dx + dy*dy + dz*dz;
        bool in = (d <= R2C);
        unsigned m = __ballot_sync(0xffffffffu, in);
        if (m) {
            int pos = cnt + __popc(m & ((1u << lane) - 1u));
            if (in && pos < KK) out[pos] = p;
            if (!have_first) { first = base + __ffs(m) - 1; have_first = true; }
            cnt += __popc(m);
            if (cnt >= KK) break;
        }
    }
    for (int pos = cnt + lane; pos < KK; pos += 32) out[pos] = first;
}

// ---------------- layer 1: gather + GEMM (K=67 -> 64) + stats ----------------
// 64 positions/block, 128 threads; thread tile 4 pos x 8 out, packed out-pairs.
__global__ __launch_bounds__(128) void layer1_kernel(
    const float* __restrict__ xyz, const float* __restrict__ points,
    const float* __restrict__ newxyz,
    const float* __restrict__ w, const float* __restrict__ bias)
{
    __shared__ __align__(16) float Xs[67][64];
    __shared__ __align__(16) float Ws[67][64];
    __shared__ __align__(16) float sh_b[64];
    __shared__ float sh_sum[64], sh_sq[64];

    int t = threadIdx.x;
    size_t pos0 = (size_t)blockIdx.x * 64;

    for (int e = t; e < 64 * 67; e += 128) {
        int o = e / 67, c = e % 67;
        Ws[c][o] = w[e];
    }
    if (t < 64) { sh_b[t] = bias[t]; sh_sum[t] = 0.f; sh_sq[t] = 0.f; }

    {   // gather: 2 threads per position
        int p = t >> 1, half = t & 1;
        size_t pos = pos0 + p;
        int j = g_idx[pos];
        int b = (int)(pos >> 15);
        int s = (int)((pos >> 5) & 1023);
        const float4* prow = (const float4*)(points + ((size_t)b * NN + j) * 64) + half * 8;
#pragma unroll
        for (int i = 0; i < 8; i++) {
            float4 v = prow[i];
            int c = 3 + half * 32 + i * 4;
            Xs[c+0][p] = v.x; Xs[c+1][p] = v.y; Xs[c+2][p] = v.z; Xs[c+3][p] = v.w;
        }
        if (!half) {
            const float* xr = xyz + ((size_t)b * NN + j) * 3;
            const float* nr = newxyz + ((size_t)b * SS + s) * 3;
            Xs[0][p] = xr[0] - nr[0];
            Xs[1][p] = xr[1] - nr[1];
            Xs[2][p] = xr[2] - nr[2];
        }
    }
    __syncthreads();

    int px = t >> 3, ox = t & 7;
    ull acc[4][4];
#pragma unroll
    for (int n = 0; n < 4; n++) {
        ull bv = *(const ull*)&sh_b[ox*8 + 2*n];
        acc[0][n] = bv; acc[1][n] = bv; acc[2][n] = bv; acc[3][n] = bv;
    }

#pragma unroll 4
    for (int c = 0; c < 67; c++) {
        float4 xv = *(const float4*)&Xs[c][px*4];
        ulonglong2 wA = *(const ulonglong2*)&Ws[c][ox*8];
        ulonglong2 wB = *(const ulonglong2*)&Ws[c][ox*8 + 4];
        ull wv[4] = {wA.x, wA.y, wB.x, wB.y};
        ull xd[4] = {dup2(xv.x), dup2(xv.y), dup2(xv.z), dup2(xv.w)};
#pragma unroll
        for (int i = 0; i < 4; i++)
#pragma unroll
            for (int n = 0; n < 4; n++)
                acc[i][n] = fma2(xd[i], wv[n], acc[i][n]);
    }

    ull s2[4], q2[4];
#pragma unroll
    for (int n = 0; n < 4; n++) { s2[n] = dup2(0.f); q2[n] = dup2(0.f); }
#pragma unroll
    for (int i = 0; i < 4; i++) {
        size_t pp = pos0 + px*4 + i;
        *(ulonglong2*)&g_y1[pp*64 + ox*8]     = make_ulonglong2(acc[i][0], acc[i][1]);
        *(ulonglong2*)&g_y1[pp*64 + ox*8 + 4] = make_ulonglong2(acc[i][2], acc[i][3]);
#pragma unroll
        for (int n = 0; n < 4; n++) {
            s2[n] = add2(s2[n], acc[i][n]);
            q2[n] = fma2(acc[i][n], acc[i][n], q2[n]);
        }
    }
#pragma unroll
    for (int n = 0; n < 4; n++) {
        float2 fs = up2(s2[n]), fq = up2(q2[n]);
        atomicAdd(&sh_sum[ox*8 + 2*n],     fs.x);
        atomicAdd(&sh_sum[ox*8 + 2*n + 1], fs.y);
        atomicAdd(&sh_sq[ox*8 + 2*n],      fq.x);
        atomicAdd(&sh_sq[ox*8 + 2*n + 1],  fq.y);
    }
    __syncthreads();
    if (t < 64) {
        atomicAdd(&g_sum[0][t], (double)sh_sum[t]);
        atomicAdd(&g_sq[0][t],  (double)sh_sq[t]);
    }
}

// ---------------- per-channel BN fold ----------------------------------------
__global__ void stats_kernel(int L, const float* __restrict__ gam,
                             const float* __restrict__ bet, int C) {
    int t = threadIdx.x;
    if (t < C) {
        double mean = g_sum[L][t] * (1.0 / (double)MTOT);
        double var  = g_sq[L][t]  * (1.0 / (double)MTOT) - mean * mean;
        float sc = gam[t] * rsqrtf((float)var + EPSC);
        g_scale[L][t] = sc;
        g_shift[L][t] = fmaf(-(float)mean, sc, bet[t]);
    }
}

// ---------------- layers 2/3: affine+relu(in) -> packed GEMM -> stats --------
// L=2: g_y1 -> g_y2 (64->64), POSB=64. L=3: g_y2 -> per-query max/min, POSB=32
// (one query per block), no y3 materialization.
template<int L, int NO, int POSB, int PX, int OX>
__global__ __launch_bounds__(PX*OX) void layer_kernel(
    const float* __restrict__ w, const float* __restrict__ bias)
{
    constexpr int THREADS = PX * OX;
    constexpr int TO = NO / OX;            // 8 (L2) or 4 (L3)
    constexpr int NP = TO / 2;             // packed out-pairs per thread
    constexpr int TPP = THREADS / POSB;
    constexpr int V4 = 16 / TPP;

    const float* xin = (L == 2) ? g_y1 : g_y2;

    __shared__ __align__(16) float Xs[64][POSB];
    __shared__ __align__(16) float Ws[64][NO];
    __shared__ __align__(16) float sh_b[NO];
    __shared__ float sh_sum[NO], sh_sq[NO], sh_scale[64], sh_shift[64];

    int t = threadIdx.x;
    size_t pos0 = (size_t)blockIdx.x * POSB;

    for (int e = t; e < NO * 64; e += THREADS) {
        int o = e >> 6, c = e & 63;
        Ws[c][o] = w[e];
    }
    if (t < NO) { sh_b[t] = bias[t]; sh_sum[t] = 0.f; sh_sq[t] = 0.f; }
    if (t < 64) { sh_scale[t] = g_scale[L-2][t]; sh_shift[t] = g_shift[L-2][t]; }
    __syncthreads();

    {   // staged input load with fused affine+relu
        int p = t / TPP, sub = t % TPP;
        const float4* row = (const float4*)(xin + (pos0 + p) * 64) + sub * V4;
#pragma unroll
        for (int i = 0; i < V4; i++) {
            float4 v = row[i];
            int c = (sub * V4 + i) * 4;
            Xs[c+0][p] = fmaxf(fmaf(v.x, sh_scale[c+0], sh_shift[c+0]), 0.f);
            Xs[c+1][p] = fmaxf(fmaf(v.y, sh_scale[c+1], sh_shift[c+1]), 0.f);
            Xs[c+2][p] = fmaxf(fmaf(v.z, sh_scale[c+2], sh_shift[c+2]), 0.f);
            Xs[c+3][p] = fmaxf(fmaf(v.w, sh_scale[c+3], sh_shift[c+3]), 0.f);
        }
    }
    __syncthreads();

    int px = t / OX, ox = t % OX;
    ull acc[4][NP];
#pragma unroll
    for (int n = 0; n < NP; n++) {
        ull bv = *(const ull*)&sh_b[ox*TO + 2*n];
        acc[0][n] = bv; acc[1][n] = bv; acc[2][n] = bv; acc[3][n] = bv;
    }

#pragma unroll 4
    for (int c = 0; c < 64; c++) {
        float4 xv = *(const float4*)&Xs[c][px*4];
        ull wv[NP];
#pragma unroll
        for (int n = 0; n < NP; n += 2) {
            ulonglong2 ww = *(const ulonglong2*)&Ws[c][ox*TO + 2*n];
            wv[n] = ww.x; wv[n+1] = ww.y;
        }
        ull xd[4] = {dup2(xv.x), dup2(xv.y), dup2(xv.z), dup2(xv.w)};
#pragma unroll
        for (int i = 0; i < 4; i++)
#pragma unroll
            for (int n = 0; n < NP; n++)
                acc[i][n] = fma2(xd[i], wv[n], acc[i][n]);
    }

    // packed stats
    ull s2[NP], q2[NP];
#pragma unroll
    for (int n = 0; n < NP; n++) { s2[n] = dup2(0.f); q2[n] = dup2(0.f); }
#pragma unroll
    for (int i = 0; i < 4; i++)
#pragma unroll
        for (int n = 0; n < NP; n++) {
            s2[n] = add2(s2[n], acc[i][n]);
            q2[n] = fma2(acc[i][n], acc[i][n], q2[n]);
        }
#pragma unroll
    for (int n = 0; n < NP; n++) {
        float2 fs = up2(s2[n]), fq = up2(q2[n]);
        atomicAdd(&sh_sum[ox*TO + 2*n],     fs.x);
        atomicAdd(&sh_sum[ox*TO + 2*n + 1], fs.y);
        atomicAdd(&sh_sq[ox*TO + 2*n],      fq.x);
        atomicAdd(&sh_sq[ox*TO + 2*n + 1],  fq.y);
    }

    if constexpr (L == 2) {
#pragma unroll
        for (int i = 0; i < 4; i++) {
            size_t pp = pos0 + px*4 + i;
#pragma unroll
            for (int n = 0; n < NP; n += 2)
                *(ulonglong2*)&g_y2[pp*NO + ox*TO + 2*n] =
                    make_ulonglong2(acc[i][n], acc[i][n+1]);
        }
        __syncthreads();
        if (t < NO) {
            atomicAdd(&g_sum[1][t], (double)sh_sum[t]);
            atomicAdd(&g_sq[1][t],  (double)sh_sq[t]);
        }
    } else {
        // L == 3: block owns query q = blockIdx.x; reduce max & min over KK=32.
        float mymax[TO], mymin[TO];
#pragma unroll
        for (int n = 0; n < NP; n++) {
            float2 v = up2(acc[0][n]);
            mymax[2*n] = v.x; mymin[2*n] = v.x;
            mymax[2*n+1] = v.y; mymin[2*n+1] = v.y;
#pragma unroll
            for (int i = 1; i < 4; i++) {
                float2 u = up2(acc[i][n]);
                mymax[2*n]   = fmaxf(mymax[2*n],   u.x);
                mymin[2*n]   = fminf(mymin[2*n],   u.x);
                mymax[2*n+1] = fmaxf(mymax[2*n+1], u.y);
                mymin[2*n+1] = fminf(mymin[2*n+1], u.y);
            }
        }
        __syncthreads();   // all Xs reads + shared-atomic stats done
        float* red = &Xs[0][0];    // reuse: [0..1023] max[px*128+ch], [1024..2047] min
        *(float4*)&red[px*128 + ox*TO] =
            make_float4(mymax[0], mymax[1], mymax[2], mymax[3]);
        *(float4*)&red[1024 + px*128 + ox*TO] =
            make_float4(mymin[0], mymin[1], mymin[2], mymin[3]);
        __syncthreads();
        size_t q = blockIdx.x;
        if (t < 128) {
            atomicAdd(&g_sum[2][t], (double)sh_sum[t]);
            atomicAdd(&g_sq[2][t],  (double)sh_sq[t]);
            float m = red[t];
#pragma unroll
            for (int p2 = 1; p2 < 8; p2++) m = fmaxf(m, red[p2*128 + t]);
            g_mx[q*128 + t] = m;
        } else {
            int ch = t - 128;
            float m = red[1024 + ch];
#pragma unroll
            for (int p2 = 1; p2 < 8; p2++) m = fminf(m, red[1024 + p2*128 + ch]);
            g_mn[q*128 + ch] = m;
        }
    }
}

// ---------------- final: affine+relu on (max,min) + transposed store ---------
// max_k relu(sc*y+sh) == relu(max(sc*mx+sh, sc*mn+sh))  (exact by monotonicity)
__global__ void final_kernel(float* __restrict__ out) {
    int b  = blockIdx.x >> 7;
    int ch = blockIdx.x & 127;
    float sc = g_scale[2][ch], sh = g_shift[2][ch];
#pragma unroll
    for (int r = 0; r < 4; r++) {
        int s = threadIdx.x + r * 256;
        size_t q = (size_t)b * 1024 + s;
        float mx = g_mx[q*128 + ch];
        float mn = g_mn[q*128 + ch];
        float v = fmaxf(fmaxf(fmaf(sc, mx, sh), fmaf(sc, mn, sh)), 0.f);
        out[OUT_OFF + ((size_t)b * 128 + ch) * SS + s] = v;
    }
}

// ---------------- launcher ----------------------------------------------------
extern "C" void kernel_launch(void* const* d_in, const int* in_sizes, int n_in,
                              void* d_out, int out_size) {
    (void)in_sizes; (void)n_in; (void)out_size;
    const float* xyz    = (const float*)d_in[0];
    const float* points = (const float*)d_in[1];
    const float* w1  = (const float*)d_in[2];
    const float* b1  = (const float*)d_in[3];
    const float* g1  = (const float*)d_in[4];
    const float* be1 = (const float*)d_in[5];
    const float* w2  = (const float*)d_in[6];
    const float* b2  = (const float*)d_in[7];
    const float* g2  = (const float*)d_in[8];
    const float* be2 = (const float*)d_in[9];
    const float* w3  = (const float*)d_in[10];
    const float* b3  = (const float*)d_in[11];
    const float* g3  = (const float*)d_in[12];
    const float* be3 = (const float*)d_in[13];
    float* out = (float*)d_out;

    init_kernel<<<1, 512>>>();
    fps_kernel<<<BB, 1024>>>(xyz);
    gather_newxyz_kernel<<<(BB*SS + 255) / 256, 256>>>(xyz, out);
    qb_kernel<<<(BB*SS) / 8, 256>>>(xyz);

    layer1_kernel<<<MTOT / 64, 128>>>(xyz, points, out, w1, b1);
    stats_kernel<<<1, 128>>>(0, g1, be1, 64);

    layer_kernel<2, 64, 64, 16, 8><<<MTOT / 64, 128>>>(w2, b2);
    stats_kernel<<<1, 128>>>(1, g2, be2, 64);

    layer_kernel<3, 128, 32, 8, 32><<<MTOT / 32, 256>>>(w3, b3);
    stats_kernel<<<1, 128>>>(2, g3, be3, 128);

    final_kernel<<<BB * 128, 256>>>(out);
}

// round 9
// speedup vs baseline: 1.5803x; 1.3472x over previous
#include <cuda_runtime.h>
#include <cuda_bf16.h>
#include <cstdint>
#include <cstddef>

#define BB 16
#define NN 8192
#define SS 1024
#define KK 32
#define R2C 0.04f          /* float(0.2**2) */
#define EPSC 1e-5f
#define MTOT (BB*SS*KK)    /* 524288 positions */
#define OUT_OFF (BB*SS*3)

typedef unsigned long long ull;

// ---------------- packed f32x2 helpers ----------------------------------------
__device__ __forceinline__ ull fma2(ull a, ull b, ull c) {
    ull d; asm("fma.rn.f32x2 %0,%1,%2,%3;" : "=l"(d) : "l"(a), "l"(b), "l"(c)); return d;
}
__device__ __forceinline__ ull mul2(ull a, ull b) {
    ull d; asm("mul.rn.f32x2 %0,%1,%2;" : "=l"(d) : "l"(a), "l"(b)); return d;
}
__device__ __forceinline__ ull add2(ull a, ull b) {
    ull d; asm("add.rn.f32x2 %0,%1,%2;" : "=l"(d) : "l"(a), "l"(b)); return d;
}
__device__ __forceinline__ ull dup2(float x) {
    ull d; asm("mov.b64 %0,{%1,%1};" : "=l"(d) : "f"(x)); return d;
}
__device__ __forceinline__ ull pk2(float lo, float hi) {
    ull d; asm("mov.b64 %0,{%1,%2};" : "=l"(d) : "f"(lo), "f"(hi)); return d;
}
__device__ __forceinline__ float2 up2(ull v) {
    float2 r; asm("mov.b64 {%0,%1},%2;" : "=f"(r.x), "=f"(r.y) : "l"(v)); return r;
}

// ---------------- HMMA / ldmatrix helpers (baseline PTX, sm_103-safe) ---------
__device__ __forceinline__ uint32_t smem_u32(const void* p) {
    uint32_t a;
    asm("{ .reg .u64 t; cvta.to.shared.u64 t, %1; cvt.u32.u64 %0, t; }" : "=r"(a) : "l"(p));
    return a;
}
__device__ __forceinline__ void ldm4(uint32_t addr, uint32_t* r) {
    asm volatile("ldmatrix.sync.aligned.m8n8.x4.shared.b16 {%0,%1,%2,%3}, [%4];"
                 : "=r"(r[0]), "=r"(r[1]), "=r"(r[2]), "=r"(r[3]) : "r"(addr));
}
__device__ __forceinline__ void mma_bf16(float* c, const uint32_t* a, const uint32_t* b) {
    asm volatile(
        "mma.sync.aligned.m16n8k16.row.col.f32.bf16.bf16.f32 "
        "{%0,%1,%2,%3}, {%4,%5,%6,%7}, {%8,%9}, {%0,%1,%2,%3};"
        : "+f"(c[0]), "+f"(c[1]), "+f"(c[2]), "+f"(c[3])
        : "r"(a[0]), "r"(a[1]), "r"(a[2]), "r"(a[3]), "r"(b[0]), "r"(b[1]));
}

// split a fp32 pair into packed bf16-high pair + fp32 lows (exact residuals)
__device__ __forceinline__ void split_pair(float a, float b, uint32_t& hi, float& la, float& lb) {
    asm("{.reg .b16 ha,hb;\n"
        " .reg .f32 fa,fb;\n"
        " cvt.rn.bf16.f32 ha, %3;\n"
        " cvt.rn.bf16.f32 hb, %4;\n"
        " mov.b32 %0, {ha,hb};\n"
        " cvt.f32.bf16 fa, ha;\n"
        " cvt.f32.bf16 fb, hb;\n"
        " sub.f32 %1, %3, fa;\n"
        " sub.f32 %2, %4, fb;}"
        : "=r"(hi), "=f"(la), "=f"(lb) : "f"(a), "f"(b));
}
__device__ __forceinline__ uint32_t pack_bf(float a, float b) {
    uint32_t r;
    asm("{.reg .b16 x,y; cvt.rn.bf16.f32 x,%1; cvt.rn.bf16.f32 y,%2; mov.b32 %0,{x,y};}"
        : "=r"(r) : "f"(a), "f"(b));
    return r;
}

// ---------------- device scratch ----------------------------------------------
__device__ int    g_fps[BB*SS];
__device__ int    g_idx[BB*SS*KK];
__device__ float  g_y1[(size_t)MTOT*64];
__device__ float  g_y2[(size_t)MTOT*64];
__device__ float  g_y3[(size_t)MTOT*128];
__device__ double g_sum[3][128];
__device__ double g_sq[3][128];
__device__ float  g_scale[3][128];
__device__ float  g_shift[3][128];

// ---------------- init --------------------------------------------------------
__global__ void init_kernel() {
    int t = blockIdx.x * blockDim.x + threadIdx.x;
    if (t < 3 * 128) {
        ((double*)g_sum)[t] = 0.0;
        ((double*)g_sq)[t]  = 0.0;
    }
}

// ---------------- farthest point sampling (packed + REDUX) -------------------
__global__ __launch_bounds__(1024) void fps_kernel(const float* __restrict__ xyz) {
    int b = blockIdx.x;
    int t = threadIdx.x;
    const float* xb = xyz + (size_t)b * NN * 3;

    ull px2[4], py2[4], pz2[4];
    float dist[8];
#pragma unroll
    for (int j = 0; j < 4; j++) {
        int p0 = t + (2*j)   * 1024;
        int p1 = t + (2*j+1) * 1024;
        px2[j] = pk2(xb[p0*3+0], xb[p1*3+0]);
        py2[j] = pk2(xb[p0*3+1], xb[p1*3+1]);
        pz2[j] = pk2(xb[p0*3+2], xb[p1*3+2]);
    }
#pragma unroll
    for (int i = 0; i < 8; i++) dist[i] = 1e10f;

    __shared__ ull s_key[32];
    __shared__ int s_far;
    if (t == 0) s_far = 0;
    __syncthreads();

    for (int it = 0; it < SS; it++) {
        int far = s_far;
        if (t == 0) g_fps[b * SS + it] = far;
        float cx = xb[far*3+0], cy = xb[far*3+1], cz = xb[far*3+2];
        ull ncx = dup2(-cx), ncy = dup2(-cy), ncz = dup2(-cz);

        float bestv = -1.0f; int besti = 0;
#pragma unroll
        for (int j = 0; j < 4; j++) {
            ull dx = add2(px2[j], ncx);
            ull dy = add2(py2[j], ncy);
            ull dz = add2(pz2[j], ncz);
            ull d2 = mul2(dx, dx);
            d2 = fma2(dy, dy, d2);
            d2 = fma2(dz, dz, d2);
            float2 dd = up2(d2);
            float n0 = fminf(dist[2*j],   dd.x);
            float n1 = fminf(dist[2*j+1], dd.y);
            dist[2*j] = n0; dist[2*j+1] = n1;
            if (n0 > bestv) { bestv = n0; besti = t + (2*j)   * 1024; }
            if (n1 > bestv) { bestv = n1; besti = t + (2*j+1) * 1024; }
        }

        unsigned bits = __float_as_uint(bestv);
        unsigned mh = __reduce_max_sync(0xffffffffu, bits);
        unsigned ml = __reduce_max_sync(0xffffffffu, (bits == mh) ? ~(unsigned)besti : 0u);
        if ((t & 31) == 0) s_key[t >> 5] = ((ull)mh << 32) | ml;
        __syncthreads();
        if (t < 32) {
            ull k = s_key[t];
            unsigned h2 = (unsigned)(k >> 32);
            unsigned m2 = __reduce_max_sync(0xffffffffu, h2);
            unsigned l2 = __reduce_max_sync(0xffffffffu, (h2 == m2) ? (unsigned)k : 0u);
            if (t == 0) s_far = (int)(~l2);
        }
        __syncthreads();
    }
}

// ---------------- gather new_xyz into output ---------------------------------
__global__ void gather_newxyz_kernel(const float* __restrict__ xyz,
                                     float* __restrict__ out) {
    int i = blockIdx.x * blockDim.x + threadIdx.x;
    if (i < BB * SS) {
        int b = i >> 10;
        int j = g_fps[i];
        const float* p = xyz + ((size_t)b * NN + j) * 3;
        out[i*3+0] = p[0];
        out[i*3+1] = p[1];
        out[i*3+2] = p[2];
    }
}

// ---------------- ball query: one warp per query, 1-deep prefetch ------------
__global__ void qb_kernel(const float* __restrict__ xyz) {
    int q = (blockIdx.x * blockDim.x + threadIdx.x) >> 5;
    int lane = threadIdx.x & 31;
    int b = q >> 10;
    const float* xb = xyz + (size_t)b * NN * 3;
    int c = g_fps[q];
    float cx = xb[c*3+0], cy = xb[c*3+1], cz = xb[c*3+2];

    int cnt = 0;
    int first = 0;
    bool have_first = false;
    int* out = g_idx + (size_t)q * KK;

    int p = lane;
    float x = xb[p*3+0], y = xb[p*3+1], z = xb[p*3+2];

    for (int base = 0; base < NN; base += 32) {
        float nx = 0.f, ny = 0.f, nz = 0.f;
        if (base + 32 < NN) {
            int pn = base + 32 + lane;
            nx = xb[pn*3+0]; ny = xb[pn*3+1]; nz = xb[pn*3+2];
        }
        float dx = x - cx, dy = y - cy, dz = z - cz;
        float d = dx*dx + dy*dy + dz*dz;
        bool in = (d <= R2C);
        unsigned m = __ballot_sync(0xffffffffu, in);
        if (m) {
            int pos = cnt + __popc(m & ((1u << lane) - 1u));
            if (in && pos < KK) out[pos] = p;
            if (!have_first) { first = base + __ffs(m) - 1; have_first = true; }
            cnt += __popc(m);
            if (cnt >= KK) break;
        }
        p = base + 32 + lane; x = nx; y = ny; z = nz;
    }
    for (int pos = cnt + lane; pos < KK; pos += 32) out[pos] = first;
}

// ---------------- layer 1: gather + GEMM (K=67 -> 64) + stats ----------------
__global__ __launch_bounds__(128) void layer1_kernel(
    const float* __restrict__ xyz, const float* __restrict__ points,
    const float* __restrict__ newxyz,
    const float* __restrict__ w, const float* __restrict__ bias)
{
    __shared__ __align__(16) float Xs[67][64];
    __shared__ __align__(16) float Ws[67][64];
    __shared__ __align__(16) float sh_b[64];
    __shared__ float sh_sum[64], sh_sq[64];

    int t = threadIdx.x;
    size_t pos0 = (size_t)blockIdx.x * 64;

    for (int e = t; e < 64 * 67; e += 128) {
        int o = e / 67, c = e % 67;
        Ws[c][o] = w[e];
    }
    if (t < 64) { sh_b[t] = bias[t]; sh_sum[t] = 0.f; sh_sq[t] = 0.f; }

    {
        int p = t >> 1, half = t & 1;
        size_t pos = pos0 + p;
        int j = g_idx[pos];
        int b = (int)(pos >> 15);
        int s = (int)((pos >> 5) & 1023);
        const float4* prow = (const float4*)(points + ((size_t)b * NN + j) * 64) + half * 8;
#pragma unroll
        for (int i = 0; i < 8; i++) {
            float4 v = prow[i];
            int c = 3 + half * 32 + i * 4;
            Xs[c+0][p] = v.x; Xs[c+1][p] = v.y; Xs[c+2][p] = v.z; Xs[c+3][p] = v.w;
        }
        if (!half) {
            const float* xr = xyz + ((size_t)b * NN + j) * 3;
            const float* nr = newxyz + ((size_t)b * SS + s) * 3;
            Xs[0][p] = xr[0] - nr[0];
            Xs[1][p] = xr[1] - nr[1];
            Xs[2][p] = xr[2] - nr[2];
        }
    }
    __syncthreads();

    int px = t >> 3, ox = t & 7;
    ull acc[4][4];
#pragma unroll
    for (int n = 0; n < 4; n++) {
        ull bv = *(const ull*)&sh_b[ox*8 + 2*n];
        acc[0][n] = bv; acc[1][n] = bv; acc[2][n] = bv; acc[3][n] = bv;
    }

#pragma unroll 4
    for (int c = 0; c < 67; c++) {
        float4 xv = *(const float4*)&Xs[c][px*4];
        ulonglong2 wA = *(const ulonglong2*)&Ws[c][ox*8];
        ulonglong2 wB = *(const ulonglong2*)&Ws[c][ox*8 + 4];
        ull wv[4] = {wA.x, wA.y, wB.x, wB.y};
        ull xd[4] = {dup2(xv.x), dup2(xv.y), dup2(xv.z), dup2(xv.w)};
#pragma unroll
        for (int i = 0; i < 4; i++)
#pragma unroll
            for (int n = 0; n < 4; n++)
                acc[i][n] = fma2(xd[i], wv[n], acc[i][n]);
    }

    ull s2[4], q2[4];
#pragma unroll
    for (int n = 0; n < 4; n++) { s2[n] = dup2(0.f); q2[n] = dup2(0.f); }
#pragma unroll
    for (int i = 0; i < 4; i++) {
        size_t pp = pos0 + px*4 + i;
        *(ulonglong2*)&g_y1[pp*64 + ox*8]     = make_ulonglong2(acc[i][0], acc[i][1]);
        *(ulonglong2*)&g_y1[pp*64 + ox*8 + 4] = make_ulonglong2(acc[i][2], acc[i][3]);
#pragma unroll
        for (int n = 0; n < 4; n++) {
            s2[n] = add2(s2[n], acc[i][n]);
            q2[n] = fma2(acc[i][n], acc[i][n], q2[n]);
        }
    }
#pragma unroll
    for (int n = 0; n < 4; n++) {
        float2 fs = up2(s2[n]), fq = up2(q2[n]);
        atomicAdd(&sh_sum[ox*8 + 2*n],     fs.x);
        atomicAdd(&sh_sum[ox*8 + 2*n + 1], fs.y);
        atomicAdd(&sh_sq[ox*8 + 2*n],      fq.x);
        atomicAdd(&sh_sq[ox*8 + 2*n + 1],  fq.y);
    }
    __syncthreads();
    if (t < 64) {
        atomicAdd(&g_sum[0][t], (double)sh_sum[t]);
        atomicAdd(&g_sq[0][t],  (double)sh_sq[t]);
    }
}

// ---------------- per-channel BN fold ----------------------------------------
__global__ void stats_kernel(int L, const float* __restrict__ gam,
                             const float* __restrict__ bet, int C) {
    int t = threadIdx.x;
    if (t < C) {
        double mean = g_sum[L][t] * (1.0 / (double)MTOT);
        double var  = g_sq[L][t]  * (1.0 / (double)MTOT) - mean * mean;
        float sc = gam[t] * rsqrtf((float)var + EPSC);
        g_scale[L][t] = sc;
        g_shift[L][t] = fmaf(-(float)mean, sc, bet[t]);
    }
}

// ---------------- layers 2/3: HMMA (mma.sync) split-bf16 GEMM ----------------
// A' = [ah | ah | al] (128 rows x 192 bf16), B' = [bh ; bl ; bh] (NCH x 192).
// y = A @ B^T + bias, fp32 accum; dropped al*bl term ~3e-5 rel.
// smem layout: K-chunked [kchunk][row][16 bf16], row stride 32B.
template<int L>
__global__ __launch_bounds__(256) void mm_kernel(const float* __restrict__ w,
                                                 const float* __restrict__ bias)
{
    constexpr int NCH  = (L == 2) ? 64 : 128;
    constexpr int LIN  = L - 2;
    constexpr int ACH  = 128 * 32;              // 4096 bytes per A k-chunk
    constexpr int ABYTES = 12 * ACH;            // 49152
    constexpr int BCH  = NCH * 32;              // B k-chunk bytes
    constexpr int BBYTES = 12 * BCH;
    constexpr int NT8  = NCH / 16;              // n8-tiles per warp (4 or 8)
    constexpr int NB4  = NT8 / 2;               // ldmatrix.x4 B loads per kstep

    const float* xin  = (L == 2) ? g_y1 : g_y2;
    float*       yout = (L == 2) ? g_y2 : g_y3;

    extern __shared__ char dsm[];
    uint32_t raw = smem_u32(dsm);
    uint32_t abase = (raw + 1023) & ~1023u;
    char* sm  = dsm + (abase - raw);
    char* Bsm = sm + ABYTES;
    uint32_t bbase = abase + ABYTES;
    float* sh_bias = (float*)(Bsm + BBYTES);
    float* sh_sc = sh_bias + NCH;
    float* sh_sf = sh_sc + 64;

    int t = threadIdx.x;
    int wid = t >> 5, lane = t & 31;
    size_t pos0 = (size_t)blockIdx.x * 128;

    if (t < NCH) sh_bias[t] = bias[t];
    if (t < 64) { sh_sc[t] = g_scale[LIN][t]; sh_sf[t] = g_shift[LIN][t]; }
    __syncthreads();

    // ---- stage A: 2 threads per row, 32 in-channels each ----
    {
        int r = t >> 1, h = t & 1;
        const float4* xrow = (const float4*)(xin + (pos0 + r) * 64) + h * 8;
#pragma unroll
        for (int g = 0; g < 8; g++) {
            float4 v = xrow[g];
            int c = h * 32 + g * 4;
            float a0 = fmaxf(fmaf(v.x, sh_sc[c+0], sh_sf[c+0]), 0.f);
            float a1 = fmaxf(fmaf(v.y, sh_sc[c+1], sh_sf[c+1]), 0.f);
            float a2 = fmaxf(fmaf(v.z, sh_sc[c+2], sh_sf[c+2]), 0.f);
            float a3 = fmaxf(fmaf(v.w, sh_sc[c+3], sh_sf[c+3]), 0.f);
            uint32_t h01, h23; float l0, l1, l2, l3;
            split_pair(a0, a1, h01, l0, l1);
            split_pair(a2, a3, h23, l2, l3);
            uint32_t lo01 = pack_bf(l0, l1), lo23 = pack_bf(l2, l3);
            uint32_t off = (uint32_t)(c >> 4) * ACH + (uint32_t)r * 32 + (uint32_t)(c & 15) * 2;
            *(uint2*)(sm + off)             = make_uint2(h01, h23);   // ah (k = c)
            *(uint2*)(sm + off + 4 * ACH)   = make_uint2(h01, h23);   // ah (k = 64+c)
            *(uint2*)(sm + off + 8 * ACH)   = make_uint2(lo01, lo23); // al (k = 128+c)
        }
    }
    // ---- stage B: weight rows split (bh | bl | bh) ----
    {
        constexpr int TPR = 256 / NCH;      // threads per weight row
        constexpr int CPT = 64 / TPR;       // in-channels per thread
        int r = t / TPR, sub = t % TPR;
        const float4* wrow = (const float4*)(w + r * 64 + sub * CPT);
#pragma unroll
        for (int g = 0; g < CPT / 4; g++) {
            float4 v = wrow[g];
            int c = sub * CPT + g * 4;
            uint32_t h01, h23; float l0, l1, l2, l3;
            split_pair(v.x, v.y, h01, l0, l1);
            split_pair(v.z, v.w, h23, l2, l3);
            uint32_t lo01 = pack_bf(l0, l1), lo23 = pack_bf(l2, l3);
            uint32_t off = (uint32_t)(c >> 4) * BCH + (uint32_t)r * 32 + (uint32_t)(c & 15) * 2;
            *(uint2*)(Bsm + off)            = make_uint2(h01, h23);   // bh
            *(uint2*)(Bsm + off + 4 * BCH)  = make_uint2(lo01, lo23); // bl
            *(uint2*)(Bsm + off + 8 * BCH)  = make_uint2(h01, h23);   // bh
        }
    }
    __syncthreads();

    // ---- warp tile: 32 rows x (NCH/2) cols ----
    int m0 = (wid & 3) * 32;
    int n0 = (wid >> 2) * (NCH / 2);

    float acc[2][NT8][4];
#pragma unroll
    for (int mi = 0; mi < 2; mi++)
#pragma unroll
        for (int nj = 0; nj < NT8; nj++)
#pragma unroll
            for (int e = 0; e < 4; e++) acc[mi][nj][e] = 0.f;

    uint32_t a_addr[2], b_addr[NB4];
#pragma unroll
    for (int mi = 0; mi < 2; mi++)
        a_addr[mi] = abase + (uint32_t)(m0 + mi*16 + (lane & 15)) * 32 + (uint32_t)(lane >> 4) * 16;
#pragma unroll
    for (int nj = 0; nj < NB4; nj++)
        b_addr[nj] = bbase + (uint32_t)(n0 + nj*16 + (lane & 7) + ((lane >> 4) << 3)) * 32
                           + (uint32_t)((lane >> 3) & 1) * 16;

#pragma unroll
    for (int kc = 0; kc < 12; kc++) {
        uint32_t af[2][4];
        ldm4(a_addr[0] + kc * ACH, af[0]);
        ldm4(a_addr[1] + kc * ACH, af[1]);
        uint32_t bf[NT8][2];
#pragma unroll
        for (int nj = 0; nj < NB4; nj++) {
            uint32_t tmp[4];
            ldm4(b_addr[nj] + kc * BCH, tmp);
            bf[2*nj][0] = tmp[0]; bf[2*nj][1] = tmp[1];
            bf[2*nj+1][0] = tmp[2]; bf[2*nj+1][1] = tmp[3];
        }
#pragma unroll
        for (int mi = 0; mi < 2; mi++)
#pragma unroll
            for (int nj = 0; nj < NT8; nj++)
                mma_bf16(acc[mi][nj], af[mi], bf[nj]);
    }

    // ---- epilogue: bias add + direct global store ----
    {
        int rq = lane >> 2;          // row within 8-group
        int cq = (lane & 3) * 2;     // col pair
#pragma unroll
        for (int mi = 0; mi < 2; mi++) {
            size_t row = pos0 + m0 + mi*16 + rq;
#pragma unroll
            for (int nj = 0; nj < NT8; nj++) {
                int col = n0 + nj*8 + cq;
                float b0 = sh_bias[col], b1 = sh_bias[col+1];
                *(float2*)(yout + row * NCH + col) =
                    make_float2(acc[mi][nj][0] + b0, acc[mi][nj][1] + b1);
                *(float2*)(yout + (row + 8) * NCH + col) =
                    make_float2(acc[mi][nj][2] + b0, acc[mi][nj][3] + b1);
            }
        }
    }
}

// ---------------- per-channel sum/sumsq reduction over y ----------------------
template<int C, int L>
__global__ __launch_bounds__(256) void redsum_kernel() {
    const float* y = (L == 1) ? g_y2 : g_y3;
    __shared__ float ss[C], sq[C];
    int t = threadIdx.x;
    if (t < C) { ss[t] = 0.f; sq[t] = 0.f; }
    __syncthreads();
    constexpr int RPB = 256 / C;
    int ch = t & (C - 1);
    int rl = t / C;
    float s = 0.f, q = 0.f;
    for (size_t row = (size_t)blockIdx.x * RPB + rl; row < MTOT;
         row += (size_t)gridDim.x * RPB) {
        float v = y[row * C + ch];
        s += v; q = fmaf(v, v, q);
    }
    atomicAdd(&ss[ch], s);
    atomicAdd(&sq[ch], q);
    __syncthreads();
    if (t < C) {
        atomicAdd(&g_sum[L][t], (double)ss[t]);
        atomicAdd(&g_sq[L][t],  (double)sq[t]);
    }
}

// ---------------- final: affine+relu + max over nsample + transpose ----------
__global__ void final_kernel(float* __restrict__ out) {
    int q = blockIdx.x;          // (b,s)
    int o = threadIdx.x;         // channel
    float sc = g_scale[2][o], sh = g_shift[2][o];
    const float* base = g_y3 + (size_t)q * KK * 128;
    float m = -3.4e38f;
#pragma unroll 8
    for (int k = 0; k < KK; k++)
        m = fmaxf(m, fmaf(base[k*128 + o], sc, sh));
    m = fmaxf(m, 0.f);
    int b = q >> 10, s = q & 1023;
    out[OUT_OFF + ((size_t)b * 128 + o) * SS + s] = m;
}

// ---------------- launcher ----------------------------------------------------
extern "C" void kernel_launch(void* const* d_in, const int* in_sizes, int n_in,
                              void* d_out, int out_size) {
    (void)in_sizes; (void)n_in; (void)out_size;
    const float* xyz    = (const float*)d_in[0];
    const float* points = (const float*)d_in[1];
    const float* w1  = (const float*)d_in[2];
    const float* b1  = (const float*)d_in[3];
    const float* g1  = (const float*)d_in[4];
    const float* be1 = (const float*)d_in[5];
    const float* w2  = (const float*)d_in[6];
    const float* b2  = (const float*)d_in[7];
    const float* g2  = (const float*)d_in[8];
    const float* be2 = (const float*)d_in[9];
    const float* w3  = (const float*)d_in[10];
    const float* b3  = (const float*)d_in[11];
    const float* g3  = (const float*)d_in[12];
    const float* be3 = (const float*)d_in[13];
    float* out = (float*)d_out;

    const int DYN2 = 1024 + 49152 + 24576 + 1024;   // 75776
    const int DYN3 = 1024 + 49152 + 49152 + 1024;   // 100352
    cudaFuncSetAttribute(mm_kernel<2>, cudaFuncAttributeMaxDynamicSharedMemorySize, DYN2);
    cudaFuncSetAttribute(mm_kernel<3>, cudaFuncAttributeMaxDynamicSharedMemorySize, DYN3);

    init_kernel<<<1, 512>>>();
    fps_kernel<<<BB, 1024>>>(xyz);
    gather_newxyz_kernel<<<(BB*SS + 255) / 256, 256>>>(xyz, out);
    qb_kernel<<<(BB*SS) / 8, 256>>>(xyz);

    layer1_kernel<<<MTOT / 64, 128>>>(xyz, points, out, w1, b1);
    stats_kernel<<<1, 128>>>(0, g1, be1, 64);

    mm_kernel<2><<<MTOT / 128, 256, DYN2>>>(w2, b2);
    redsum_kernel<64, 1><<<512, 256>>>();
    stats_kernel<<<1, 128>>>(1, g2, be2, 64);

    mm_kernel<3><<<MTOT / 128, 256, DYN3>>>(w3, b3);
    redsum_kernel<128, 2><<<512, 256>>>();
    stats_kernel<<<1, 128>>>(2, g3, be3, 128);

    final_kernel<<<BB * SS, 128>>>(out);
}